// round 1
// baseline (speedup 1.0000x reference)
#include <cuda_runtime.h>
#include <cstddef>

// ---------------------------------------------------------------------------
// SLAYER SRM-alpha SNN, fused implementation.
// Layers:  psp -> conv1 -> [spike+psp] -> pool -> [spike+psp] -> conv2 ->
//          [spike+psp] -> pool -> [spike+psp] -> conv3 -> [spike+psp] ->
//          dense -> spike
// Layout: [N,C,H,W,T] with T innermost (stride 1), T = 300, N = 8.
// ---------------------------------------------------------------------------

#define T_LEN 300
#define TC4   75              // T/4 float4 chunks
#define NBATCH 8

typedef unsigned long long ull;

// Neuron/sim constants (float32, matching jnp casts of python doubles)
#define C_DS 0.90483741803595952f     // exp(-1/10)
#define C_B  0.27182818284590452f     // e/10
#define C_DR 0.36787944117144233f     // exp(-1)
#define C_A  (-54.365636569180902f)   // -2*10*e
#define C_TH 10.0f
#define C_POOL 11.0f                  // 1.1*theta -> 11.0f in f32

// Scratch ping-pong buffers (max live tensor: 8*16*28*28*300 = 30,105,600 f32)
#define BUF_ELEMS 30105600
__device__ float g_bufA[BUF_ELEMS];
__device__ float g_bufB[BUF_ELEMS];

// packed f32x2 FMA (sm_100+ PTX). Bit layout of ulonglong2 == float4.
__device__ __forceinline__ ull ffma2(ull a, ull b, ull c) {
    ull d;
    asm("fma.rn.f32x2 %0, %1, %2, %3;" : "=l"(d) : "l"(a), "l"(b), "l"(c));
    return d;
}

// ---------------------------------------------------------------------------
// Temporal scan kernel. MODE: 0 = psp only, 1 = spike then psp (fused),
// 2 = spike only. One thread per neuron; 128-neuron x 32-t tiles staged in
// smem for coalescing. T contiguous per neuron.
// ---------------------------------------------------------------------------
template<int MODE>
__global__ __launch_bounds__(128)
void scan_kernel(const float* __restrict__ x, float* __restrict__ y,
                 int numNeurons) {
    __shared__ float tile[128][33];
    const int tid  = threadIdx.x;
    const int lane = tid & 31;
    const int warp = tid >> 5;
    const int nb   = blockIdx.x * 128;
    const int myN  = nb + tid;
    const bool active = myN < numNeurons;

    float p_r = 0.f, q_r = 0.f, p_s = 0.f, q_s = 0.f;

    for (int tbase = 0; tbase < T_LEN; tbase += 32) {
        const int cl = min(32, T_LEN - tbase);
        // coalesced load: each warp iteration fetches one neuron's 32 t's
        #pragma unroll 8
        for (int k = 0; k < 32; k++) {
            int nrn = k * 4 + warp;
            int gn  = nb + nrn;
            if (gn < numNeurons && lane < cl)
                tile[nrn][lane] = x[(size_t)gn * T_LEN + tbase + lane];
        }
        __syncthreads();
        if (active) {
            for (int k = 0; k < cl; k++) {
                float u = tile[tid][k];
                float outv;
                if (MODE == 0) {
                    q_s = C_DS * (q_s + p_s);
                    p_s = C_DS * p_s + u;
                    outv = C_B * q_s;
                } else {
                    q_r = C_DR * (q_r + p_r);
                    float v = u + C_A * q_r;
                    float s = (v >= C_TH) ? 1.0f : 0.0f;
                    p_r = C_DR * p_r + s;
                    if (MODE == 1) {
                        q_s = C_DS * (q_s + p_s);
                        p_s = C_DS * p_s + s;
                        outv = C_B * q_s;
                    } else {
                        outv = s;
                    }
                }
                tile[tid][k] = outv;
            }
        }
        __syncthreads();
        #pragma unroll 8
        for (int k = 0; k < 32; k++) {
            int nrn = k * 4 + warp;
            int gn  = nb + nrn;
            if (gn < numNeurons && lane < cl)
                y[(size_t)gn * T_LEN + tbase + lane] = tile[nrn][lane];
        }
        __syncthreads();
    }
}

// ---------------------------------------------------------------------------
// Direct conv, per-timestep 2D, vectorized over t (float4 = 2 x f32x2).
// Thread = (n, oy, ox, tc); computes CO_BLK output channels; weights
// pre-duplicated in smem as float2 for direct f32x2 FMA operands.
// gridDim.y = CO / CO_BLK output-channel groups.
// ---------------------------------------------------------------------------
template<int CI, int CO, int CO_BLK, int K, int H, int W, int OH, int OW, int PAD>
__global__ __launch_bounds__(256)
void conv_kernel(const float* __restrict__ x, const float* __restrict__ wgt,
                 float* __restrict__ y) {
    constexpr int TAPS = CI * K * K;
    __shared__ float2 ws[CO_BLK * TAPS];
    const int oBase = blockIdx.y * CO_BLK;
    for (int i = threadIdx.x; i < CO_BLK * TAPS; i += blockDim.x) {
        float v = wgt[oBase * TAPS + i];
        ws[i] = make_float2(v, v);
    }
    __syncthreads();

    long long g = (long long)blockIdx.x * blockDim.x + threadIdx.x;
    int tc = (int)(g % TC4); long long r = g / TC4;
    int ox = (int)(r % OW); r /= OW;
    int oy = (int)(r % OH); r /= OH;
    int n  = (int)r;
    if (n >= NBATCH) return;

    ulonglong2 acc[CO_BLK];
    #pragma unroll
    for (int o = 0; o < CO_BLK; o++) acc[o] = make_ulonglong2(0ULL, 0ULL);

    const float* xb = x + (size_t)n * CI * H * W * T_LEN + tc * 4;

    for (int ci = 0; ci < CI; ci++) {
        #pragma unroll
        for (int kh = 0; kh < K; kh++) {
            int iy = oy + kh - PAD;
            if ((unsigned)iy >= (unsigned)H) continue;
            #pragma unroll
            for (int kw = 0; kw < K; kw++) {
                int ix = ox + kw - PAD;
                if ((unsigned)ix >= (unsigned)W) continue;
                const ulonglong2 xv =
                    *(const ulonglong2*)(xb + ((size_t)(ci * H + iy) * W + ix) * T_LEN);
                const int tap = (ci * K + kh) * K + kw;
                #pragma unroll
                for (int o = 0; o < CO_BLK; o++) {
                    ull w2 = *(const ull*)&ws[o * TAPS + tap];
                    acc[o].x = ffma2(w2, xv.x, acc[o].x);
                    acc[o].y = ffma2(w2, xv.y, acc[o].y);
                }
            }
        }
    }
    #pragma unroll
    for (int o = 0; o < CO_BLK; o++) {
        size_t off = (((size_t)(n * CO + oBase + o) * OH + oy) * OW + ox) * T_LEN
                     + tc * 4;
        *(ulonglong2*)(y + off) = acc[o];
    }
}

// ---------------------------------------------------------------------------
// 2x2 sum-pool * 11.0, vectorized float4 over t.
// ---------------------------------------------------------------------------
__global__ __launch_bounds__(256)
void pool_kernel(const float* __restrict__ x, float* __restrict__ y,
                 int C, int OH, int OW) {
    long long total = (long long)NBATCH * C * OH * OW * TC4;
    long long g = (long long)blockIdx.x * blockDim.x + threadIdx.x;
    if (g >= total) return;
    int tc = (int)(g % TC4); long long r = g / TC4;
    int ox = (int)(r % OW); r /= OW;
    int oy = (int)(r % OH); r /= OH;
    int c  = (int)(r % C);
    int n  = (int)(r / C);
    const int H = OH * 2, W = OW * 2;
    const float* b = x + (((size_t)(n * C + c) * H + oy * 2) * W + ox * 2) * T_LEN
                     + tc * 4;
    float4 a0 = *(const float4*)b;
    float4 a1 = *(const float4*)(b + T_LEN);
    float4 a2 = *(const float4*)(b + (size_t)W * T_LEN);
    float4 a3 = *(const float4*)(b + (size_t)(W + 1) * T_LEN);
    float4 o4;
    o4.x = (a0.x + a1.x + a2.x + a3.x) * C_POOL;
    o4.y = (a0.y + a1.y + a2.y + a3.y) * C_POOL;
    o4.z = (a0.z + a1.z + a2.z + a3.z) * C_POOL;
    o4.w = (a0.w + a1.w + a2.w + a3.w) * C_POOL;
    size_t off = (((size_t)(n * C + c) * OH + oy) * OW + ox) * T_LEN + tc * 4;
    *(float4*)(y + off) = o4;
}

// ---------------------------------------------------------------------------
// Dense over (C,H,W)=3136 per timestep: x [8,64,7,7,300], w [10,3136] -> [8,10,300]
// Thread per (n,o,t): warp-contiguous over t -> coalesced x loads, broadcast w.
// ---------------------------------------------------------------------------
__global__ __launch_bounds__(256)
void dense_kernel(const float* __restrict__ x, const float* __restrict__ wgt,
                  float* __restrict__ y) {
    int g = blockIdx.x * blockDim.x + threadIdx.x;
    if (g >= NBATCH * 10 * T_LEN) return;
    int t = g % T_LEN; int r = g / T_LEN;
    int o = r % 10;    int n = r / 10;
    const float* xb = x + (size_t)n * 3136 * T_LEN + t;
    const float* wb = wgt + o * 3136;
    float acc = 0.f;
    #pragma unroll 8
    for (int i = 0; i < 3136; i++)
        acc = fmaf(wb[i], xb[(size_t)i * T_LEN], acc);
    y[g] = acc;
}

// ---------------------------------------------------------------------------

static inline int cdiv(long long a, long long b) { return (int)((a + b - 1) / b); }

extern "C" void kernel_launch(void* const* d_in, const int* in_sizes, int n_in,
                              void* d_out, int out_size) {
    const float* in = (const float*)d_in[0];   // [8,1,30,30,300]
    const float* w1 = (const float*)d_in[1];   // [16,1,5,5]
    const float* w2 = (const float*)d_in[2];   // [32,16,3,3]
    const float* w3 = (const float*)d_in[3];   // [64,32,3,3]
    const float* w4 = (const float*)d_in[4];   // [10,64,7,7]
    float* out = (float*)d_out;                // [8,10,300]

    float *bufA, *bufB;
    cudaGetSymbolAddress((void**)&bufA, g_bufA);
    cudaGetSymbolAddress((void**)&bufB, g_bufB);

    // 1) P0 = psp(input)          [8,1,30,30,300]  neurons = 7200
    scan_kernel<0><<<cdiv(7200, 128), 128>>>(in, bufA, 7200);

    // 2) U1 = conv1(P0)           [8,16,28,28,300]
    conv_kernel<1, 16, 16, 5, 30, 30, 28, 28, 1>
        <<<dim3(cdiv((long long)NBATCH * 28 * 28 * TC4, 256), 1), 256>>>(bufA, w1, bufB);

    // 3) Q1 = psp(spike(U1))      neurons = 100352
    scan_kernel<1><<<cdiv(100352, 128), 128>>>(bufB, bufA, 100352);

    // 4) U2 = pool(Q1)            [8,16,14,14,300]
    pool_kernel<<<cdiv((long long)NBATCH * 16 * 14 * 14 * TC4, 256), 256>>>(bufA, bufB, 16, 14, 14);

    // 5) Q2 = psp(spike(U2))      neurons = 25088
    scan_kernel<1><<<cdiv(25088, 128), 128>>>(bufB, bufA, 25088);

    // 6) U3 = conv2(Q2)           [8,32,14,14,300]
    conv_kernel<16, 32, 16, 3, 14, 14, 14, 14, 1>
        <<<dim3(cdiv((long long)NBATCH * 14 * 14 * TC4, 256), 2), 256>>>(bufA, w2, bufB);

    // 7) Q3 = psp(spike(U3))      neurons = 50176
    scan_kernel<1><<<cdiv(50176, 128), 128>>>(bufB, bufA, 50176);

    // 8) U4 = pool(Q3)            [8,32,7,7,300]
    pool_kernel<<<cdiv((long long)NBATCH * 32 * 7 * 7 * TC4, 256), 256>>>(bufA, bufB, 32, 7, 7);

    // 9) Q4 = psp(spike(U4))      neurons = 12544
    scan_kernel<1><<<cdiv(12544, 128), 128>>>(bufB, bufA, 12544);

    // 10) U5 = conv3(Q4)          [8,64,7,7,300]
    conv_kernel<32, 64, 16, 3, 7, 7, 7, 7, 1>
        <<<dim3(cdiv((long long)NBATCH * 7 * 7 * TC4, 256), 4), 256>>>(bufA, w3, bufB);

    // 11) Q5 = psp(spike(U5))     neurons = 25088
    scan_kernel<1><<<cdiv(25088, 128), 128>>>(bufB, bufA, 25088);

    // 12) U6 = dense(Q5)          [8,10,300]
    dense_kernel<<<cdiv(NBATCH * 10 * T_LEN, 256), 256>>>(bufA, w4, bufB);

    // 13) out = spike(U6)         neurons = 80
    scan_kernel<2><<<1, 128>>>(bufB, out, 80);
}